// round 12
// baseline (speedup 1.0000x reference)
#include <cuda_runtime.h>
#include <cuda_bf16.h>
#include <cstdint>

// Problem constants (fixed by the reference):
//   T=20 timesteps, G=1024 groups, P=64 peds/group, THR=0.25
//   out[g*P*P*T + (i*P+j)*T + t] = relu(THR - sqrt(dist2 + (i==j)))
// trajectory_relative and seq_start_end are unused (uniform contiguous groups).
//
// Structure (settled over R1-R11):
//  - per-group tile in smem, pedestrian-major (LDS.128-friendly)
//  - thread = (j, t-chunk); operand b_j register-resident (f32x2, negated)
//  - sweep i; 1 LDS.128-pair + 1 STG.128 per output float4
//  - stores: warp = 512 B contiguous; DEFAULT cache policy (this round's
//    experiment: let dirty output lines persist in L2 across graph replays)
//  - branchless diagonal via +1 under the sqrt (reference's own identity trick)

#define TT 20
#define GG 1024
#define PP 64
#define THRC 0.25f
#define NTHREADS 320          // 64 j * 5 t-chunks
#define ISPLIT 2              // blocks per group along i
#define IPB (PP / ISPLIT)     // 32 i-iterations per block

// smem tile: pedestrian-major, row padded to 22 float2 = 176 B (16B multiple)
#define TPAD 22

__device__ __forceinline__ uint64_t f32x2_add(uint64_t a, uint64_t b) {
    uint64_t r;
    asm("add.rn.f32x2 %0, %1, %2;" : "=l"(r) : "l"(a), "l"(b));
    return r;
}
__device__ __forceinline__ uint64_t f32x2_mul(uint64_t a, uint64_t b) {
    uint64_t r;
    asm("mul.rn.f32x2 %0, %1, %2;" : "=l"(r) : "l"(a), "l"(b));
    return r;
}
__device__ __forceinline__ float2 unpack_f32x2(uint64_t v) {
    float lo, hi;
    asm("mov.b64 {%0, %1}, %2;" : "=f"(lo), "=f"(hi) : "l"(v));
    return make_float2(lo, hi);
}
__device__ __forceinline__ uint64_t pack_f32x2(float lo, float hi) {
    uint64_t r;
    asm("mov.b64 %0, {%1, %2};" : "=l"(r) : "f"(lo), "f"(hi));
    return r;
}
__device__ __forceinline__ float sqrt_approx(float x) {
    float r;
    asm("sqrt.approx.f32 %0, %1;" : "=f"(r) : "f"(x));
    return r;
}

__global__ __launch_bounds__(NTHREADS)
void traj_cost_kernel(const float2* __restrict__ traj, float* __restrict__ out) {
    const int g = blockIdx.y;
    const int i0 = blockIdx.x * IPB;

    __shared__ float2 xs[PP][TPAD];   // [pedestrian][timestep]

    // Load group slab, transposing t-major global -> p-major smem.
    const float2* gsrc = traj + (size_t)g * PP;
    #pragma unroll
    for (int idx = threadIdx.x; idx < TT * PP; idx += NTHREADS) {
        int t = idx >> 6;          // /64
        int p = idx & (PP - 1);    // %64
        xs[p][t] = gsrc[(size_t)t * (GG * PP) + p];
    }
    __syncthreads();

    // Thread identity: tid = j*5 + m  (j = other pedestrian, m = t-chunk)
    const int j  = threadIdx.x / 5;
    const int m  = threadIdx.x - j * 5;
    const int t0 = m << 2;

    // Operand b_j: this thread's 4 timesteps, negated and packed as f32x2,
    // kept in registers for all i.
    const float4* bp = reinterpret_cast<const float4*>(&xs[j][t0]);
    const float4 b01 = bp[0];   // (x_t0, y_t0, x_t0+1, y_t0+1)
    const float4 b23 = bp[1];
    const uint64_t nb0 = pack_f32x2(-b01.x, -b01.y);
    const uint64_t nb1 = pack_f32x2(-b01.z, -b01.w);
    const uint64_t nb2 = pack_f32x2(-b23.x, -b23.y);
    const uint64_t nb3 = pack_f32x2(-b23.z, -b23.w);

    // Store base: out[g*P*P*T + i*P*T + j*T + t0]; per warp this is 512 B
    // contiguous (tid*16 B), perfectly coalesced STG.128.
    float* gout = out + (size_t)g * (PP * PP * TT) + (size_t)j * TT + t0
                + (size_t)i0 * (PP * TT);

    #pragma unroll 4
    for (int ii = 0; ii < IPB; ii++) {
        const int i = i0 + ii;

        const ulonglong2* ap = reinterpret_cast<const ulonglong2*>(&xs[i][t0]);
        ulonglong2 a01 = ap[0];   // .x=(x_t0,y_t0)  .y=(x_t0+1,y_t0+1)
        ulonglong2 a23 = ap[1];

        // Branchless diagonal: +1 under the sqrt when i==j, so
        // relu(THR - sqrt(0+1)) == 0 exactly (matches reference identity add).
        const float diag = (i == j) ? 1.0f : 0.0f;

        uint64_t d0 = f32x2_add(a01.x, nb0);
        uint64_t d1 = f32x2_add(a01.y, nb1);
        uint64_t d2 = f32x2_add(a23.x, nb2);
        uint64_t d3 = f32x2_add(a23.y, nb3);

        uint64_t s0 = f32x2_mul(d0, d0);
        uint64_t s1 = f32x2_mul(d1, d1);
        uint64_t s2 = f32x2_mul(d2, d2);
        uint64_t s3 = f32x2_mul(d3, d3);

        float2 q0 = unpack_f32x2(s0);
        float2 q1 = unpack_f32x2(s1);
        float2 q2 = unpack_f32x2(s2);
        float2 q3 = unpack_f32x2(s3);

        float4 v;
        v.x = fmaxf(0.0f, THRC - sqrt_approx(q0.x + q0.y + diag));
        v.y = fmaxf(0.0f, THRC - sqrt_approx(q1.x + q1.y + diag));
        v.z = fmaxf(0.0f, THRC - sqrt_approx(q2.x + q2.y + diag));
        v.w = fmaxf(0.0f, THRC - sqrt_approx(q3.x + q3.y + diag));

        // Default-policy store: allow dirty output lines to linger in L2 so
        // the next graph replay can overwrite them without a DRAM round trip.
        *reinterpret_cast<float4*>(gout + (size_t)ii * (PP * TT)) = v;
    }
}

extern "C" void kernel_launch(void* const* d_in, const int* in_sizes, int n_in,
                              void* d_out, int out_size) {
    const float2* traj = (const float2*)d_in[0];  // trajectory (T, G*P, 2)
    float* out = (float*)d_out;                    // (G*P*P*T) fp32

    dim3 grid(ISPLIT, GG);
    traj_cost_kernel<<<grid, NTHREADS>>>(traj, out);
}

// round 13
// speedup vs baseline: 1.0768x; 1.0768x over previous
#include <cuda_runtime.h>
#include <cuda_bf16.h>
#include <cstdint>

// Problem constants (fixed by the reference):
//   T=20 timesteps, G=1024 groups, P=64 peds/group, THR=0.25
//   out[g*P*P*T + (i*P+j)*T + t] = relu(THR - sqrt(dist2 + (i==j)))
// trajectory_relative and seq_start_end are unused (uniform contiguous groups).
//
// FINAL (settled over R1-R12, bench 54.0us, at the HBM write-stream ceiling):
//  - per-group tile in smem, pedestrian-major (LDS.128-friendly)
//  - thread = (j, t-chunk); operand b_j register-resident (f32x2, negated)
//  - sweep i; 1 LDS.128-pair + 1 STG.128 per output float4
//  - stores: warp = 512 B contiguous, streaming (.cs) — verified 3.4us better
//    than default policy (the 335 MB stream thrashes L2 LRU either way; .cs
//    keeps the input tile resident and drains writebacks promptly)
//  - branchless diagonal via +1 under the sqrt (reference's own identity trick)

#define TT 20
#define GG 1024
#define PP 64
#define THRC 0.25f
#define NTHREADS 320          // 64 j * 5 t-chunks
#define ISPLIT 2              // blocks per group along i
#define IPB (PP / ISPLIT)     // 32 i-iterations per block

// smem tile: pedestrian-major, row padded to 22 float2 = 176 B (16B multiple)
#define TPAD 22

__device__ __forceinline__ uint64_t f32x2_add(uint64_t a, uint64_t b) {
    uint64_t r;
    asm("add.rn.f32x2 %0, %1, %2;" : "=l"(r) : "l"(a), "l"(b));
    return r;
}
__device__ __forceinline__ uint64_t f32x2_mul(uint64_t a, uint64_t b) {
    uint64_t r;
    asm("mul.rn.f32x2 %0, %1, %2;" : "=l"(r) : "l"(a), "l"(b));
    return r;
}
__device__ __forceinline__ float2 unpack_f32x2(uint64_t v) {
    float lo, hi;
    asm("mov.b64 {%0, %1}, %2;" : "=f"(lo), "=f"(hi) : "l"(v));
    return make_float2(lo, hi);
}
__device__ __forceinline__ uint64_t pack_f32x2(float lo, float hi) {
    uint64_t r;
    asm("mov.b64 %0, {%1, %2};" : "=l"(r) : "f"(lo), "f"(hi));
    return r;
}
__device__ __forceinline__ float sqrt_approx(float x) {
    float r;
    asm("sqrt.approx.f32 %0, %1;" : "=f"(r) : "f"(x));
    return r;
}

__global__ __launch_bounds__(NTHREADS)
void traj_cost_kernel(const float2* __restrict__ traj, float* __restrict__ out) {
    const int g = blockIdx.y;
    const int i0 = blockIdx.x * IPB;

    __shared__ float2 xs[PP][TPAD];   // [pedestrian][timestep]

    // Load group slab, transposing t-major global -> p-major smem.
    const float2* gsrc = traj + (size_t)g * PP;
    #pragma unroll
    for (int idx = threadIdx.x; idx < TT * PP; idx += NTHREADS) {
        int t = idx >> 6;          // /64
        int p = idx & (PP - 1);    // %64
        xs[p][t] = gsrc[(size_t)t * (GG * PP) + p];
    }
    __syncthreads();

    // Thread identity: tid = j*5 + m  (j = other pedestrian, m = t-chunk)
    const int j  = threadIdx.x / 5;
    const int m  = threadIdx.x - j * 5;
    const int t0 = m << 2;

    // Operand b_j: this thread's 4 timesteps, negated and packed as f32x2,
    // kept in registers for all i.
    const float4* bp = reinterpret_cast<const float4*>(&xs[j][t0]);
    const float4 b01 = bp[0];   // (x_t0, y_t0, x_t0+1, y_t0+1)
    const float4 b23 = bp[1];
    const uint64_t nb0 = pack_f32x2(-b01.x, -b01.y);
    const uint64_t nb1 = pack_f32x2(-b01.z, -b01.w);
    const uint64_t nb2 = pack_f32x2(-b23.x, -b23.y);
    const uint64_t nb3 = pack_f32x2(-b23.z, -b23.w);

    // Store base: out[g*P*P*T + i*P*T + j*T + t0]; per warp this is 512 B
    // contiguous (tid*16 B), perfectly coalesced STG.128.
    float* gout = out + (size_t)g * (PP * PP * TT) + (size_t)j * TT + t0
                + (size_t)i0 * (PP * TT);

    #pragma unroll 4
    for (int ii = 0; ii < IPB; ii++) {
        const int i = i0 + ii;

        const ulonglong2* ap = reinterpret_cast<const ulonglong2*>(&xs[i][t0]);
        ulonglong2 a01 = ap[0];   // .x=(x_t0,y_t0)  .y=(x_t0+1,y_t0+1)
        ulonglong2 a23 = ap[1];

        // Branchless diagonal: +1 under the sqrt when i==j, so
        // relu(THR - sqrt(0+1)) == 0 exactly (matches reference identity add).
        const float diag = (i == j) ? 1.0f : 0.0f;

        uint64_t d0 = f32x2_add(a01.x, nb0);
        uint64_t d1 = f32x2_add(a01.y, nb1);
        uint64_t d2 = f32x2_add(a23.x, nb2);
        uint64_t d3 = f32x2_add(a23.y, nb3);

        uint64_t s0 = f32x2_mul(d0, d0);
        uint64_t s1 = f32x2_mul(d1, d1);
        uint64_t s2 = f32x2_mul(d2, d2);
        uint64_t s3 = f32x2_mul(d3, d3);

        float2 q0 = unpack_f32x2(s0);
        float2 q1 = unpack_f32x2(s1);
        float2 q2 = unpack_f32x2(s2);
        float2 q3 = unpack_f32x2(s3);

        float4 v;
        v.x = fmaxf(0.0f, THRC - sqrt_approx(q0.x + q0.y + diag));
        v.y = fmaxf(0.0f, THRC - sqrt_approx(q1.x + q1.y + diag));
        v.z = fmaxf(0.0f, THRC - sqrt_approx(q2.x + q2.y + diag));
        v.w = fmaxf(0.0f, THRC - sqrt_approx(q3.x + q3.y + diag));

        // Streaming store: output is write-once, keep it out of L2's way.
        __stcs(reinterpret_cast<float4*>(gout + (size_t)ii * (PP * TT)), v);
    }
}

extern "C" void kernel_launch(void* const* d_in, const int* in_sizes, int n_in,
                              void* d_out, int out_size) {
    const float2* traj = (const float2*)d_in[0];  // trajectory (T, G*P, 2)
    float* out = (float*)d_out;                    // (G*P*P*T) fp32

    dim3 grid(ISPLIT, GG);
    traj_cost_kernel<<<grid, NTHREADS>>>(traj, out);
}